// round 9
// baseline (speedup 1.0000x reference)
#include <cuda_runtime.h>
#include <cuda_bf16.h>
#include <math.h>
typedef __nv_bfloat16 bf;
#define NB 148
#define NT 256
#define LOOKN 10
#define LE 48
#define MM2 12288
#define KTG 1152

// ---------------- device scratch ----------------
__device__ bf g_WtgH[2048*KTG], g_WtgL[2048*KTG];
__device__ bf g_WspH[2048*1024], g_WspL[2048*1024];
__device__ bf g_WmidH[2048*1024], g_WmidL[2048*1024];
__device__ bf g_WthH[1024*1024], g_WthL[1024*1024];
__device__ bf g_WeH[512*1024], g_WeL[512*1024];
__device__ bf g_VdH[512*512], g_VdL[512*512];
__device__ bf g_WxH[512*512], g_WxL[512*512];
__device__ bf g_WiH[512*512], g_WiL[512*512];
__device__ bf g_InH[MM2*512], g_InL[MM2*512];
__device__ bf g_AtgH[256*KTG], g_AtgL[256*KTG];
__device__ bf g_HtH[256*512], g_HtL[256*512];
__device__ bf g_CtH[256*512], g_CtL[256*512];
__device__ bf g_HeH[2][256*512], g_HeL[2][256*512];
__device__ bf g_CeH[256*512], g_CeL[256*512];
__device__ bf g_HmH[2][256*512], g_HmL[2][256*512];
__device__ bf g_XmH[256*512], g_XmL[256*512];
__device__ bf g_UH[256*512], g_UL[256*512];
__device__ bf g_MidH[LE*256*512], g_MidL[LE*256*512];
__device__ bf g_M2H[MM2*512], g_M2L[MM2*512];
__device__ float g_bt[2048], g_bs[2048], g_bm[2048];
__device__ float g_wi[MM2*512], g_mid2[MM2*512], g_u2[MM2*512];
__device__ float g_ht[256*512], g_ct[256*512], g_ce[256*512], g_cm[256*512];
__device__ float g_dec[256*512], g_wtwh[256*1024], g_score[256*512];
__device__ float g_lab[256], g_sc[MM2];
__device__ unsigned g_bc, g_bg;

__device__ __forceinline__ void gridbar(unsigned &gen) {
    __syncthreads();
    if (threadIdx.x == 0) {
        __threadfence();
        if (atomicAdd(&g_bc, 1u) == (unsigned)(NB - 1)) {
            g_bc = 0u; __threadfence();
            atomicExch(&g_bg, gen + 1u);
        } else {
            unsigned v;
            do {
                asm volatile("ld.acquire.gpu.global.u32 %0, [%1];" : "=r"(v) : "l"(&g_bg));
            } while (v == gen);
        }
        __threadfence();
    }
    __syncthreads();
    gen++;
}
__device__ __forceinline__ float sigm(float x) { return 1.f / (1.f + expf(-x)); }
__device__ __forceinline__ void bsplit(float x, bf &h, bf &l) {
    h = __float2bfloat16(x);
    l = __float2bfloat16(x - __bfloat162float(h));
}
__device__ __forceinline__ unsigned su32(const void* p) {
    return (unsigned)__cvta_generic_to_shared(p);
}
__device__ __forceinline__ void ldsm4(unsigned a, unsigned* r) {
    asm volatile("ldmatrix.sync.aligned.m8n8.x4.shared.b16 {%0,%1,%2,%3}, [%4];"
                 : "=r"(r[0]), "=r"(r[1]), "=r"(r[2]), "=r"(r[3]) : "r"(a));
}
__device__ __forceinline__ void mma16816(float* d, const unsigned* a, const unsigned* b) {
    asm volatile("mma.sync.aligned.m16n8k16.row.col.f32.bf16.bf16.f32 "
                 "{%0,%1,%2,%3}, {%4,%5,%6,%7}, {%8,%9}, {%0,%1,%2,%3};"
                 : "+f"(d[0]), "+f"(d[1]), "+f"(d[2]), "+f"(d[3])
                 : "r"(a[0]), "r"(a[1]), "r"(a[2]), "r"(a[3]), "r"(b[0]), "r"(b[1]));
}
__device__ __forceinline__ void cpa16(unsigned d, const void* s) {
    asm volatile("cp.async.cg.shared.global [%0], [%1], 16;" :: "r"(d), "l"(s));
}
__device__ __forceinline__ void cpcommit() { asm volatile("cp.async.commit_group;"); }
template<int N> __device__ __forceinline__ void cpwait() {
    asm volatile("cp.async.wait_group %0;" :: "n"(N));
}

// -------- TC tile engine: (MI*32)m x 64n, 8 warps (2m x 4n), split-bf16 3-pass.
// K staged 128/stage, 3-buffer circular cp.async pipeline, 1 sync per stage.
template <int MI, int CAT2>
__device__ void tc_tile(float acc[][2][4], int bm, int bn, int K,
                        const bf* __restrict__ A0h, const bf* __restrict__ A0l,
                        const bf* __restrict__ A1h, const bf* __restrict__ A1l,
                        const bf* __restrict__ Bh, const bf* __restrict__ Bl, char* sm) {
    const int TM = MI * 32;
    const unsigned BUF = (unsigned)(2 * TM + 128) * 272;
    const int tid = threadIdx.x, lane = tid & 31, w = tid >> 5;
    const unsigned sb = su32(sm);
#pragma unroll
    for (int mi = 0; mi < MI; mi++)
#pragma unroll
        for (int nf = 0; nf < 2; nf++)
#pragma unroll
            for (int k = 0; k < 4; k++) acc[mi][nf][k] = 0.f;
    const int ns = K >> 7;
    auto stage = [&](int st) {
        unsigned base = sb + (unsigned)(st % 3) * BUF;
        int k0 = st << 7;
#pragma unroll
        for (int c = tid; c < TM * 32; c += NT) {
            int p = c >= TM * 16 ? 1 : 0;
            int cc = c - p * TM * 16;
            int row = cc >> 4, q = cc & 15;
            int gk = k0 + q * 8;
            const bf* src;
            if (CAT2) src = (gk < 512) ? ((p ? A0l : A0h) + (size_t)(bm + row) * 512 + gk)
                                       : ((p ? A1l : A1h) + (size_t)(bm + row) * 512 + gk - 512);
            else      src = (p ? A0l : A0h) + (size_t)(bm + row) * K + gk;
            cpa16(base + (unsigned)(p * TM + row) * 272 + q * 16, src);
        }
        unsigned bb = base + (unsigned)(2 * TM) * 272;
#pragma unroll
        for (int c = tid; c < 2048; c += NT) {
            int p = c >> 10, row = (c >> 4) & 63, q = c & 15;
            cpa16(bb + (unsigned)(p * 64 + row) * 272 + q * 16,
                  (p ? Bl : Bh) + (size_t)(bn + row) * K + k0 + q * 8);
        }
        cpcommit();
    };
    stage(0); stage(1);
    const unsigned offA = (unsigned)((w & 1) * (MI * 16) + (lane & 15)) * 272 + (lane >> 4) * 16;
    const unsigned offB = (unsigned)(2 * TM) * 272
                        + (unsigned)((w >> 1) * 16 + ((lane >> 4) << 3) + (lane & 7)) * 272
                        + ((lane >> 3) & 1) * 16;
    for (int st = 0; st < ns; st++) {
        if (st + 1 < ns) cpwait<1>(); else cpwait<0>();
        __syncthreads();
        if (st + 2 < ns) stage(st + 2);
        unsigned base = sb + (unsigned)(st % 3) * BUF;
#pragma unroll
        for (int kk = 0; kk < 8; kk++) {
            unsigned aH[MI][4], aL[MI][4], bH[4], bL[4];
#pragma unroll
            for (int mi = 0; mi < MI; mi++) {
                ldsm4(base + offA + (unsigned)(mi * 16) * 272 + kk * 32, aH[mi]);
                ldsm4(base + offA + (unsigned)(TM + mi * 16) * 272 + kk * 32, aL[mi]);
            }
            ldsm4(base + offB + kk * 32, bH);
            ldsm4(base + offB + (unsigned)64 * 272 + kk * 32, bL);
#pragma unroll
            for (int mi = 0; mi < MI; mi++)
#pragma unroll
                for (int nf = 0; nf < 2; nf++) {
                    mma16816(acc[mi][nf], aH[mi], bH + 2 * nf);
                    mma16816(acc[mi][nf], aH[mi], bL + 2 * nf);
                    mma16816(acc[mi][nf], aL[mi], bH + 2 * nf);
                }
        }
    }
    __syncthreads();
}

// ---------------- epilogues ----------------
template <int MI>
__device__ void epi_store(float acc[][2][4], int bm, int bn, float* C, int ldc,
                          const float* bias) {
    int lane = threadIdx.x & 31, w = threadIdx.x >> 5;
    int wm = (w & 1) * (MI * 16), wn = (w >> 1) * 16;
#pragma unroll
    for (int mi = 0; mi < MI; mi++)
#pragma unroll
        for (int nf = 0; nf < 2; nf++)
#pragma unroll
            for (int k = 0; k < 4; k++) {
                int m = bm + wm + mi * 16 + (lane >> 2) + (k >> 1) * 8;
                int nc = bn + wn + nf * 8 + (lane & 3) * 2 + (k & 1);
                float v = acc[mi][nf][k];
                if (bias) v += bias[nc];
                C[(size_t)m * ldc + nc] = v;
            }
}
template <int MI>
__device__ void epi_u(float acc[][2][4], int bm, int bn, int l) {
    int lane = threadIdx.x & 31, w = threadIdx.x >> 5;
    int wm = (w & 1) * (MI * 16), wn = (w >> 1) * 16;
#pragma unroll
    for (int mi = 0; mi < MI; mi++)
#pragma unroll
        for (int nf = 0; nf < 2; nf++)
#pragma unroll
            for (int k = 0; k < 4; k++) {
                int m = bm + wm + mi * 16 + (lane >> 2) + (k >> 1) * 8;
                int nc = bn + wn + nf * 8 + (lane & 3) * 2 + (k & 1);
                float v = tanhf(acc[mi][nf][k] + g_wi[((size_t)m * 48 + l) * 512 + nc]
                                + g_wtwh[(size_t)m * 1024 + nc]);
                size_t ix = ((size_t)m << 9) + nc;
                bsplit(v, g_UH[ix], g_UL[ix]);
            }
}
template <int MI>
__device__ void epi_u2(float acc[][2][4], int bm, int bn, const float* wxb) {
    int lane = threadIdx.x & 31, w = threadIdx.x >> 5;
    int wm = (w & 1) * (MI * 16), wn = (w >> 1) * 16;
#pragma unroll
    for (int mi = 0; mi < MI; mi++)
#pragma unroll
        for (int nf = 0; nf < 2; nf++)
#pragma unroll
            for (int k = 0; k < 4; k++) {
                int m = bm + wm + mi * 16 + (lane >> 2) + (k >> 1) * 8;
                int nc = bn + wn + nf * 8 + (lane & 3) * 2 + (k & 1);
                float v = tanhf(acc[mi][nf][k] + wxb[nc]
                                + g_wtwh[(size_t)(m / 48) * 1024 + 512 + nc]);
                g_u2[(size_t)m * 512 + nc] = v;
            }
}
// interleaved-gate LSTM epilogue (B rows packed n' = j*4 + gate)
template <int MI>
__device__ void epi_lstm(float acc[][2][4], int bm, int bn, const float* bias,
                         float* cP, float* hF, bf* hH, bf* hL, bf* cH, bf* cL,
                         float* eF, bf* eH, bf* eL, size_t eOff, int eStr) {
    int lane = threadIdx.x & 31, w = threadIdx.x >> 5;
    int wm = (w & 1) * (MI * 16), wn = (w >> 1) * 16;
    int q = lane & 3;
#pragma unroll
    for (int mi = 0; mi < MI; mi++)
#pragma unroll
        for (int nf = 0; nf < 2; nf++)
#pragma unroll
            for (int rh = 0; rh < 2; rh++) {
                float va = acc[mi][nf][rh * 2 + 0], vb = acc[mi][nf][rh * 2 + 1];
                float pa = __shfl_xor_sync(0xffffffffu, va, 1);
                float pb = __shfl_xor_sync(0xffffffffu, vb, 1);
                if (!(q & 1)) {
                    int m = bm + wm + mi * 16 + (lane >> 2) + rh * 8;
                    int j = (bn + wn + nf * 8 + q * 2) >> 2;
                    float gi = va + bias[j], gf = vb + bias[512 + j];
                    float gg = pa + bias[1024 + j], go = pb + bias[1536 + j];
                    size_t ix = ((size_t)m << 9) + j;
                    float c2 = sigm(gf) * cP[ix] + sigm(gi) * tanhf(gg);
                    float hn = sigm(go) * tanhf(c2);
                    cP[ix] = c2;
                    bf hh, hl; bsplit(hn, hh, hl);
                    hH[ix] = hh; hL[ix] = hl;
                    if (hF) hF[ix] = hn;
                    if (cH) { bf ch, cl; bsplit(c2, ch, cl); cH[ix] = ch; cL[ix] = cl; }
                    if (eH) {
                        size_t ex = (size_t)m * eStr + eOff + j;
                        eH[ex] = hh; eL[ex] = hl;
                        if (eF) eF[ex] = hn;
                    }
                }
            }
}

// ---------------- megakernel ----------------
__global__ void __launch_bounds__(NT, 1)
mega(const float* __restrict__ input, const float* __restrict__ label_p,
     const float* __restrict__ Wih_sp, const float* __restrict__ Whh_sp,
     const float* __restrict__ bih_sp, const float* __restrict__ bhh_sp,
     const float* __restrict__ Wih_tg, const float* __restrict__ Whh_tg,
     const float* __restrict__ bih_tg, const float* __restrict__ bhh_tg,
     const float* __restrict__ Wih_mid, const float* __restrict__ Whh_mid,
     const float* __restrict__ bih_mid, const float* __restrict__ bhh_mid,
     const float* __restrict__ Wi_w, const float* __restrict__ Wi_b,
     const float* __restrict__ We_w, const float* __restrict__ Wt_w,
     const float* __restrict__ Vd_w, const float* __restrict__ Vd_b,
     const float* __restrict__ Wx_w, const float* __restrict__ Wx_b,
     const float* __restrict__ Wh_w, const float* __restrict__ V_w,
     const float* __restrict__ V_b, const float* __restrict__ reg_w,
     const float* __restrict__ reg_b, float* __restrict__ out) {
    extern __shared__ char sm[];
    float* smf = (float*)sm;
    unsigned gen = *((volatile unsigned*)&g_bg);
    const int tid = threadIdx.x;
    const int gtid = blockIdx.x * NT + tid;
    const int gs = NB * NT;
    const int lane = tid & 31, w = tid >> 5;
    const bf z = __float2bfloat16(0.f);

    // ---- S0: split/pack weights, biases, init ----
    for (int i = gtid; i < 2048 * KTG; i += gs) {
        int np = i / KTG, cc = i - np * KTG;
        int r = (np & 3) * 512 + (np >> 2);
        float v = 0.f;
        if (cc < 513)       v = Wih_tg[r * 513 + cc];
        else if (cc < 1025) v = Whh_tg[(r << 9) + cc - 513];
        bsplit(v, g_WtgH[i], g_WtgL[i]);
    }
    for (int i = gtid; i < 2048 * 1024; i += gs) {
        int np = i >> 10, cc = i & 1023;
        int r = (np & 3) * 512 + (np >> 2);
        float vs = cc < 512 ? Wih_sp[(r << 9) + cc] : Whh_sp[(r << 9) + cc - 512];
        float vm = cc < 512 ? Wih_mid[(r << 9) + cc] : Whh_mid[(r << 9) + cc - 512];
        bsplit(vs, g_WspH[i], g_WspL[i]);
        bsplit(vm, g_WmidH[i], g_WmidL[i]);
    }
    for (int i = gtid; i < 1024 * 1024; i += gs) {
        int r = i >> 10, cc = i & 1023;
        float v = r < 512 ? Wt_w[(r << 10) + cc] : Wh_w[((r - 512) << 10) + cc];
        bsplit(v, g_WthH[i], g_WthL[i]);
    }
    for (int i = gtid; i < 512 * 1024; i += gs) bsplit(We_w[i], g_WeH[i], g_WeL[i]);
    for (int i = gtid; i < 512 * 512; i += gs) {
        bsplit(Vd_w[i], g_VdH[i], g_VdL[i]);
        bsplit(Wx_w[i], g_WxH[i], g_WxL[i]);
        bsplit(Wi_w[i], g_WiH[i], g_WiL[i]);
    }
    for (int i = gtid; i < MM2 * 512; i += gs) bsplit(input[i], g_InH[i], g_InL[i]);
    for (int i = gtid; i < 2048; i += gs) {
        g_bt[i] = bih_tg[i] + bhh_tg[i];
        g_bs[i] = bih_sp[i] + bhh_sp[i];
        g_bm[i] = bih_mid[i] + bhh_mid[i];
    }
    for (int i = gtid; i < 256 * 512; i += gs) { g_ht[i] = 0.f; g_ct[i] = 0.f; g_dec[i] = 0.f; }
    for (int i = gtid; i < 256; i += gs) g_lab[i] = label_p[i * (LE + LOOKN) + LE];
    gridbar(gen);

    // ---- S1: wi = input @ Wi^T + Wi_b (12288x512x512), MI=2 ----
    for (int _t = blockIdx.x; _t < 1536; _t += NB) {
        int bm = (_t >> 3) * 64, bn = (_t & 7) * 64;
        float acc[2][2][4];
        tc_tile<2, 0>(acc, bm, bn, 512, g_InH, g_InL, 0, 0, g_WiH, g_WiL, sm);
        epi_store<2>(acc, bm, bn, g_wi, 512, Wi_b);
    }
    gridbar(gen);

#pragma unroll 1
    for (int t = 0; t < LOOKN; t++) {
        // PA: pack Atg (split, zero-padded to KTG)
        for (int i = gtid; i < 256 * KTG; i += gs) {
            int b = i / KTG, c = i - b * KTG;
            float v = 0.f;
            if (c == 0)        v = g_lab[b];
            else if (c < 513)  v = g_dec[(b << 9) + c - 1];
            else if (c < 1025) v = g_ht[(b << 9) + c - 513];
            bsplit(v, g_AtgH[i], g_AtgL[i]);
        }
        gridbar(gen);
        // P1: tg gates + LSTM (MI=2, 128 tiles)
        for (int _t = blockIdx.x; _t < 128; _t += NB) {
            int bm = (_t >> 5) * 64, bn = (_t & 31) * 64;
            float acc[2][2][4];
            tc_tile<2, 0>(acc, bm, bn, KTG, g_AtgH, g_AtgL, 0, 0, g_WtgH, g_WtgL, sm);
            epi_lstm<2>(acc, bm, bn, g_bt, g_ct, g_ht, g_HtH, g_HtL, g_CtH, g_CtL,
                        0, 0, 0, 0, 0);
        }
        gridbar(gen);
        // P2: wtwh (MI=1, 128 tiles) + target rowdot + zero inner states
        for (int _t = blockIdx.x; _t < 128; _t += NB) {
            int bm = (_t >> 4) * 32, bn = (_t & 15) * 64;
            float acc[1][2][4];
            tc_tile<1, 1>(acc, bm, bn, 1024, g_HtH, g_HtL, g_CtH, g_CtL, g_WthH, g_WthL, sm);
            epi_store<1>(acc, bm, bn, g_wtwh, 1024, 0);
        }
        for (int u = blockIdx.x; u < 32; u += NB) {
            int row = u * 8 + w;
            const float* x = g_ht + ((size_t)row << 9);
            float s = 0.f;
#pragma unroll
            for (int k = lane * 4; k < 512; k += 128) {
                float4 xv = *(const float4*)(x + k);
                float4 wv = *(const float4*)(reg_w + k);
                s = fmaf(xv.x, wv.x, s); s = fmaf(xv.y, wv.y, s);
                s = fmaf(xv.z, wv.z, s); s = fmaf(xv.w, wv.w, s);
            }
#pragma unroll
            for (int o = 16; o; o >>= 1) s += __shfl_xor_sync(0xffffffffu, s, o);
            if (lane == 0) { s += reg_b[0]; out[row * LOOKN + t] = s; g_lab[row] = s; }
        }
        for (int i = gtid; i < 256 * 512; i += gs) {
            g_ce[i] = 0.f; g_cm[i] = 0.f;
            g_HeH[0][i] = z; g_HeL[0][i] = z;
            g_CeH[i] = z;    g_CeL[i] = z;
            g_HmH[0][i] = z; g_HmL[0][i] = z;
        }
        gridbar(gen);

        // ---- sp attention loop ----
#pragma unroll 1
        for (int l = 0; l < LE; l++) {
            const int cur = l & 1, nxt = cur ^ 1;
            // P3: u = tanh([he|ce]@We^T + wi_l + wt) (MI=1, 64 tiles)
            for (int _t = blockIdx.x; _t < 64; _t += NB) {
                int bm = (_t >> 3) * 32, bn = (_t & 7) * 64;
                float acc[1][2][4];
                tc_tile<1, 1>(acc, bm, bn, 1024, g_HeH[cur], g_HeL[cur], g_CeH, g_CeL,
                              g_WeH, g_WeL, sm);
                epi_u<1>(acc, bm, bn, l);
            }
            gridbar(gen);
            // P4: score = u @ Vd^T + Vd_b (MI=1, 64 tiles)
            for (int _t = blockIdx.x; _t < 64; _t += NB) {
                int bm = (_t >> 3) * 32, bn = (_t & 7) * 64;
                float acc[1][2][4];
                tc_tile<1, 0>(acc, bm, bn, 512, g_UH, g_UL, 0, 0, g_VdH, g_VdL, sm);
                epi_store<1>(acc, bm, bn, g_score, 512, Vd_b);
            }
            gridbar(gen);
            // P5: xmod = x * softmax(score), warp-per-row
            for (int rr = blockIdx.x * 8 + w; rr < 256; rr += NB * 8) {
                const float* srow = g_score + ((size_t)rr << 9);
                float vals[16];
                float mx = -1e30f;
#pragma unroll
                for (int i = 0; i < 16; i++) {
                    vals[i] = srow[lane + i * 32];
                    mx = fmaxf(mx, vals[i]);
                }
#pragma unroll
                for (int o = 16; o; o >>= 1) mx = fmaxf(mx, __shfl_xor_sync(0xffffffffu, mx, o));
                float sv = 0.f;
#pragma unroll
                for (int i = 0; i < 16; i++) { vals[i] = expf(vals[i] - mx); sv += vals[i]; }
#pragma unroll
                for (int o = 16; o; o >>= 1) sv += __shfl_xor_sync(0xffffffffu, sv, o);
                float inv = 1.f / sv;
                const float* xr = input + ((size_t)rr * 48 + l) * 512;
#pragma unroll
                for (int i = 0; i < 16; i++) {
                    int c = lane + i * 32;
                    bsplit(xr[c] * vals[i] * inv,
                           g_XmH[((size_t)rr << 9) + c], g_XmL[((size_t)rr << 9) + c]);
                }
            }
            gridbar(gen);
            // P6: sp gates + LSTM (MI=2, 128 tiles)
            for (int _t = blockIdx.x; _t < 128; _t += NB) {
                int bm = (_t >> 5) * 64, bn = (_t & 31) * 64;
                float acc[2][2][4];
                tc_tile<2, 1>(acc, bm, bn, 1024, g_XmH, g_XmL, g_HeH[cur], g_HeL[cur],
                              g_WspH, g_WspL, sm);
                epi_lstm<2>(acc, bm, bn, g_bs, g_ce, 0, g_HeH[nxt], g_HeL[nxt],
                            g_CeH, g_CeL, 0, g_MidH, g_MidL, (size_t)l * 131072, 512);
            }
            gridbar(gen);
        }

        // ---- mid LSTM loop ----
#pragma unroll 1
        for (int l = 0; l < LE; l++) {
            const int cur = l & 1, nxt = cur ^ 1;
            for (int _t = blockIdx.x; _t < 128; _t += NB) {
                int bm = (_t >> 5) * 64, bn = (_t & 31) * 64;
                float acc[2][2][4];
                tc_tile<2, 1>(acc, bm, bn, 1024, g_MidH + (size_t)l * 131072,
                              g_MidL + (size_t)l * 131072, g_HmH[cur], g_HmL[cur],
                              g_WmidH, g_WmidL, sm);
                epi_lstm<2>(acc, bm, bn, g_bm, g_cm, 0, g_HmH[nxt], g_HmL[nxt],
                            0, 0, g_mid2, g_M2H, g_M2L, (size_t)l * 512, LE * 512);
            }
            gridbar(gen);
        }

        // P8: u2 = tanh(mid2 @ Wx^T + Wx_b + wh) (MI=2, 1536 tiles)
        for (int _t = blockIdx.x; _t < 1536; _t += NB) {
            int bm = (_t >> 3) * 64, bn = (_t & 7) * 64;
            float acc[2][2][4];
            tc_tile<2, 0>(acc, bm, bn, 512, g_M2H, g_M2L, 0, 0, g_WxH, g_WxL, sm);
            epi_u2<2>(acc, bm, bn, Wx_b);
        }
        gridbar(gen);
        // P9: sc = u2 @ V_w + V_b
        for (int u = blockIdx.x; u < MM2 / 8; u += NB) {
            int row = u * 8 + w;
            const float* x = g_u2 + ((size_t)row << 9);
            float s = 0.f;
#pragma unroll
            for (int k = lane * 4; k < 512; k += 128) {
                float4 xv = *(const float4*)(x + k);
                float4 wv = *(const float4*)(V_w + k);
                s = fmaf(xv.x, wv.x, s); s = fmaf(xv.y, wv.y, s);
                s = fmaf(xv.z, wv.z, s); s = fmaf(xv.w, wv.w, s);
            }
#pragma unroll
            for (int o = 16; o; o >>= 1) s += __shfl_xor_sync(0xffffffffu, s, o);
            if (lane == 0) g_sc[row] = s + V_b[0];
        }
        gridbar(gen);
        // P10: dec_in
        for (int b = blockIdx.x; b < 256; b += NB) {
            __syncthreads();
            if (tid < LE) smf[tid] = g_sc[b * LE + tid];
            __syncthreads();
            for (int h2 = tid; h2 < 512; h2 += NT) {
                float s = 0.f;
                const float* m2 = g_mid2 + (size_t)b * LE * 512 + h2;
#pragma unroll 8
                for (int ll = 0; ll < LE; ll++) s = fmaf(smf[ll], m2[(size_t)ll * 512], s);
                g_dec[(b << 9) + h2] = s;
            }
        }
        gridbar(gen);
    }
}

extern "C" void kernel_launch(void* const* d_in, const int* in_sizes, int n_in,
                              void* d_out, int out_size) {
    cudaFuncSetAttribute(mega, cudaFuncAttributeMaxDynamicSharedMemorySize, 208896);
    mega<<<NB, NT, 208896>>>(
        (const float*)d_in[0],  (const float*)d_in[1],  (const float*)d_in[2],
        (const float*)d_in[3],  (const float*)d_in[4],  (const float*)d_in[5],
        (const float*)d_in[6],  (const float*)d_in[7],  (const float*)d_in[8],
        (const float*)d_in[9],  (const float*)d_in[10], (const float*)d_in[11],
        (const float*)d_in[12], (const float*)d_in[13], (const float*)d_in[14],
        (const float*)d_in[15], (const float*)d_in[16], (const float*)d_in[17],
        (const float*)d_in[18], (const float*)d_in[19], (const float*)d_in[20],
        (const float*)d_in[21], (const float*)d_in[22], (const float*)d_in[23],
        (const float*)d_in[24], (const float*)d_in[25], (const float*)d_in[26],
        (float*)d_out);
}

// round 14
// speedup vs baseline: 1.0198x; 1.0198x over previous
#include <cuda_runtime.h>
#include <cuda_bf16.h>
#include <math.h>
typedef __nv_bfloat16 bf;
#define NB 148
#define NT 512
#define LOOKN 10
#define LE 48
#define MM2 12288
#define KTG 1152

// ---------------- device scratch ----------------
__device__ bf g_WtgH[2048*KTG], g_WtgL[2048*KTG];
__device__ bf g_WspH[2048*1024], g_WspL[2048*1024];
__device__ bf g_WmidH[2048*1024], g_WmidL[2048*1024];
__device__ bf g_WthH[1024*1024], g_WthL[1024*1024];
__device__ bf g_WeH[512*1024], g_WeL[512*1024];
__device__ bf g_VdH[512*512], g_VdL[512*512];
__device__ bf g_WxH[512*512], g_WxL[512*512];
__device__ bf g_WiH[512*512], g_WiL[512*512];
__device__ bf g_InH[MM2*512], g_InL[MM2*512];
__device__ bf g_AtgH[256*KTG], g_AtgL[256*KTG];
__device__ bf g_HtH[256*512], g_HtL[256*512];
__device__ bf g_CtH[256*512], g_CtL[256*512];
__device__ bf g_HeH[2][256*512], g_HeL[2][256*512];
__device__ bf g_CeH[256*512], g_CeL[256*512];
__device__ bf g_HmH[2][256*512], g_HmL[2][256*512];
__device__ bf g_XmH[256*512], g_XmL[256*512];
__device__ bf g_UH[256*512], g_UL[256*512];
__device__ bf g_MidH[LE*256*512], g_MidL[LE*256*512];
__device__ bf g_M2H[MM2*512], g_M2L[MM2*512];
__device__ float g_bt[2048], g_bs[2048], g_bm[2048];
__device__ float g_wi[MM2*512], g_mid2[MM2*512], g_u2[MM2*512];
__device__ float g_ht[256*512], g_ct[256*512], g_ce[256*512], g_cm[256*512];
__device__ float g_dec[256*512], g_wtwh[256*1024], g_score[256*512];
__device__ float g_lab[256], g_sc[MM2];
__device__ unsigned g_bc, g_bg;

__device__ __forceinline__ void gridbar(unsigned &gen) {
    __syncthreads();
    if (threadIdx.x == 0) {
        __threadfence();
        if (atomicAdd(&g_bc, 1u) == (unsigned)(NB - 1)) {
            g_bc = 0u; __threadfence();
            atomicExch(&g_bg, gen + 1u);
        } else {
            unsigned v;
            do {
                asm volatile("ld.acquire.gpu.global.u32 %0, [%1];" : "=r"(v) : "l"(&g_bg));
            } while (v == gen);
        }
        __threadfence();
    }
    __syncthreads();
    gen++;
}
__device__ __forceinline__ float sigm(float x) { return 1.f / (1.f + expf(-x)); }
__device__ __forceinline__ void bsplit(float x, bf &h, bf &l) {
    h = __float2bfloat16(x);
    l = __float2bfloat16(x - __bfloat162float(h));
}
__device__ __forceinline__ unsigned su32(const void* p) {
    return (unsigned)__cvta_generic_to_shared(p);
}
__device__ __forceinline__ void ldsm4(unsigned a, unsigned* r) {
    asm volatile("ldmatrix.sync.aligned.m8n8.x4.shared.b16 {%0,%1,%2,%3}, [%4];"
                 : "=r"(r[0]), "=r"(r[1]), "=r"(r[2]), "=r"(r[3]) : "r"(a));
}
__device__ __forceinline__ void ldsm2(unsigned a, unsigned* r) {
    asm volatile("ldmatrix.sync.aligned.m8n8.x2.shared.b16 {%0,%1}, [%2];"
                 : "=r"(r[0]), "=r"(r[1]) : "r"(a));
}
__device__ __forceinline__ void mma16816(float* d, const unsigned* a, const unsigned* b) {
    asm volatile("mma.sync.aligned.m16n8k16.row.col.f32.bf16.bf16.f32 "
                 "{%0,%1,%2,%3}, {%4,%5,%6,%7}, {%8,%9}, {%0,%1,%2,%3};"
                 : "+f"(d[0]), "+f"(d[1]), "+f"(d[2]), "+f"(d[3])
                 : "r"(a[0]), "r"(a[1]), "r"(a[2]), "r"(a[3]), "r"(b[0]), "r"(b[1]));
}
__device__ __forceinline__ void cpa16(unsigned d, const void* s) {
    asm volatile("cp.async.cg.shared.global [%0], [%1], 16;" :: "r"(d), "l"(s));
}
__device__ __forceinline__ void cpcommit() { asm volatile("cp.async.commit_group;"); }
template<int N> __device__ __forceinline__ void cpwait() {
    asm volatile("cp.async.wait_group %0;" :: "n"(N));
}

// warp tile origin helpers (16 warps)
template <int TM> __device__ __forceinline__ int wm_of(int w) {
    return (TM == 64) ? (w & 3) * 16 : (w & 1) * 16;
}
template <int TM> __device__ __forceinline__ int wn_of(int w) {
    return (TM == 64) ? (w >> 2) * 16 : (w >> 1) * 8;
}

// -------- TC tile engine: TMm x 64n, 16 warps, split-bf16 3-pass,
// K staged 128/stage, 3-buffer circular cp.async pipeline.
template <int TM, int CAT2>
__device__ void tc_tile(float acc[][4], int bm, int bn, int K,
                        const bf* __restrict__ A0h, const bf* __restrict__ A0l,
                        const bf* __restrict__ A1h, const bf* __restrict__ A1l,
                        const bf* __restrict__ Bh, const bf* __restrict__ Bl, char* sm) {
    const int NF = (TM == 64) ? 2 : 1;
    const unsigned BUF = (unsigned)(2 * TM + 128) * 272;
    const int tid = threadIdx.x, lane = tid & 31, w = tid >> 5;
    const unsigned sb = su32(sm);
#pragma unroll
    for (int nf = 0; nf < NF; nf++)
#pragma unroll
        for (int k = 0; k < 4; k++) acc[nf][k] = 0.f;
    const int ns = K >> 7;
    auto stage = [&](int st) {
        unsigned base = sb + (unsigned)(st % 3) * BUF;
        int k0 = st << 7;
#pragma unroll
        for (int c = tid; c < TM * 32; c += NT) {
            int p = c >= TM * 16 ? 1 : 0;
            int cc = c - p * TM * 16;
            int row = cc >> 4, q = cc & 15;
            int gk = k0 + q * 8;
            const bf* src;
            if (CAT2) src = (gk < 512) ? ((p ? A0l : A0h) + (size_t)(bm + row) * 512 + gk)
                                       : ((p ? A1l : A1h) + (size_t)(bm + row) * 512 + gk - 512);
            else      src = (p ? A0l : A0h) + (size_t)(bm + row) * K + gk;
            cpa16(base + (unsigned)(p * TM + row) * 272 + q * 16, src);
        }
        unsigned bb = base + (unsigned)(2 * TM) * 272;
#pragma unroll
        for (int c = tid; c < 2048; c += NT) {
            int p = c >> 10, row = (c >> 4) & 63, q = c & 15;
            cpa16(bb + (unsigned)(p * 64 + row) * 272 + q * 16,
                  (p ? Bl : Bh) + (size_t)(bn + row) * K + k0 + q * 8);
        }
        cpcommit();
    };
    stage(0); if (ns > 1) stage(1);
    const int wm = wm_of<TM>(w), wn = wn_of<TM>(w);
    const unsigned offA = (unsigned)(wm + (lane & 15)) * 272 + (lane >> 4) * 16;
    unsigned offB;
    if (TM == 64) {
        offB = (unsigned)(2 * TM) * 272
             + (unsigned)(wn + ((lane >> 4) << 3) + (lane & 7)) * 272 + ((lane >> 3) & 1) * 16;
    } else {
        int l15 = lane & 15;
        offB = (unsigned)(2 * TM) * 272 + (unsigned)(wn + (l15 & 7)) * 272 + (l15 >> 3) * 16;
    }
    for (int st = 0; st < ns; st++) {
        if (st + 1 < ns) cpwait<1>(); else cpwait<0>();
        __syncthreads();
        if (st + 2 < ns) stage(st + 2);
        unsigned base = sb + (unsigned)(st % 3) * BUF;
#pragma unroll
        for (int kk = 0; kk < 8; kk++) {
            unsigned aH[4], aL[4], bH[4], bL[4];
            ldsm4(base + offA + kk * 32, aH);
            ldsm4(base + offA + (unsigned)TM * 272 + kk * 32, aL);
            if (TM == 64) {
                ldsm4(base + offB + kk * 32, bH);
                ldsm4(base + offB + (unsigned)64 * 272 + kk * 32, bL);
            } else {
                ldsm2(base + offB + kk * 32, bH);
                ldsm2(base + offB + (unsigned)64 * 272 + kk * 32, bL);
            }
#pragma unroll
            for (int nf = 0; nf < NF; nf++) {
                mma16816(acc[nf], aH, bH + 2 * nf);
                mma16816(acc[nf], aH, bL + 2 * nf);
                mma16816(acc[nf], aL, bH + 2 * nf);
            }
        }
    }
    __syncthreads();
}

// ---------------- epilogues ----------------
template <int TM>
__device__ void epi_store(float acc[][4], int bm, int bn, float* C, int ldc,
                          const float* bias) {
    const int NF = (TM == 64) ? 2 : 1;
    int lane = threadIdx.x & 31, w = threadIdx.x >> 5;
    int wm = wm_of<TM>(w), wn = wn_of<TM>(w);
#pragma unroll
    for (int nf = 0; nf < NF; nf++)
#pragma unroll
        for (int k = 0; k < 4; k++) {
            int m = bm + wm + (lane >> 2) + (k >> 1) * 8;
            int nc = bn + wn + nf * 8 + (lane & 3) * 2 + (k & 1);
            float v = acc[nf][k];
            if (bias) v += bias[nc];
            C[(size_t)m * ldc + nc] = v;
        }
}
template <int TM>
__device__ void epi_u(float acc[][4], int bm, int bn, int l) {
    const int NF = (TM == 64) ? 2 : 1;
    int lane = threadIdx.x & 31, w = threadIdx.x >> 5;
    int wm = wm_of<TM>(w), wn = wn_of<TM>(w);
#pragma unroll
    for (int nf = 0; nf < NF; nf++)
#pragma unroll
        for (int k = 0; k < 4; k++) {
            int m = bm + wm + (lane >> 2) + (k >> 1) * 8;
            int nc = bn + wn + nf * 8 + (lane & 3) * 2 + (k & 1);
            float v = tanhf(acc[nf][k] + g_wi[((size_t)m * 48 + l) * 512 + nc]
                            + g_wtwh[(size_t)m * 1024 + nc]);
            size_t ix = ((size_t)m << 9) + nc;
            bsplit(v, g_UH[ix], g_UL[ix]);
        }
}
template <int TM>
__device__ void epi_u2(float acc[][4], int bm, int bn, const float* wxb) {
    const int NF = (TM == 64) ? 2 : 1;
    int lane = threadIdx.x & 31, w = threadIdx.x >> 5;
    int wm = wm_of<TM>(w), wn = wn_of<TM>(w);
#pragma unroll
    for (int nf = 0; nf < NF; nf++)
#pragma unroll
        for (int k = 0; k < 4; k++) {
            int m = bm + wm + (lane >> 2) + (k >> 1) * 8;
            int nc = bn + wn + nf * 8 + (lane & 3) * 2 + (k & 1);
            float v = tanhf(acc[nf][k] + wxb[nc]
                            + g_wtwh[(size_t)(m / 48) * 1024 + 512 + nc]);
            g_u2[(size_t)m * 512 + nc] = v;
        }
}
// interleaved-gate LSTM epilogue (B rows packed n' = j*4 + gate)
template <int TM>
__device__ void epi_lstm(float acc[][4], int bm, int bn, const float* bias,
                         float* cP, float* hF, bf* hH, bf* hL, bf* cH, bf* cL,
                         float* eF, bf* eH, bf* eL, size_t eOff, int eStr) {
    const int NF = (TM == 64) ? 2 : 1;
    int lane = threadIdx.x & 31, w = threadIdx.x >> 5;
    int wm = wm_of<TM>(w), wn = wn_of<TM>(w);
    int q = lane & 3;
#pragma unroll
    for (int nf = 0; nf < NF; nf++)
#pragma unroll
        for (int rh = 0; rh < 2; rh++) {
            float va = acc[nf][rh * 2 + 0], vb = acc[nf][rh * 2 + 1];
            float pa = __shfl_xor_sync(0xffffffffu, va, 1);
            float pb = __shfl_xor_sync(0xffffffffu, vb, 1);
            if (!(q & 1)) {
                int m = bm + wm + (lane >> 2) + rh * 8;
                int j = (bn + wn + nf * 8 + q * 2) >> 2;
                float gi = va + bias[j], gf = vb + bias[512 + j];
                float gg = pa + bias[1024 + j], go = pb + bias[1536 + j];
                size_t ix = ((size_t)m << 9) + j;
                float c2 = sigm(gf) * cP[ix] + sigm(gi) * tanhf(gg);
                float hn = sigm(go) * tanhf(c2);
                cP[ix] = c2;
                bf hh, hl; bsplit(hn, hh, hl);
                hH[ix] = hh; hL[ix] = hl;
                if (hF) hF[ix] = hn;
                if (cH) { bf ch, cl; bsplit(c2, ch, cl); cH[ix] = ch; cL[ix] = cl; }
                if (eH) {
                    size_t ex = (size_t)m * eStr + eOff + j;
                    eH[ex] = hh; eL[ex] = hl;
                    if (eF) eF[ex] = hn;
                }
            }
        }
}

// ---------------- megakernel ----------------
__global__ void __launch_bounds__(NT, 1)
mega(const float* __restrict__ input, const float* __restrict__ label_p,
     const float* __restrict__ Wih_sp, const float* __restrict__ Whh_sp,
     const float* __restrict__ bih_sp, const float* __restrict__ bhh_sp,
     const float* __restrict__ Wih_tg, const float* __restrict__ Whh_tg,
     const float* __restrict__ bih_tg, const float* __restrict__ bhh_tg,
     const float* __restrict__ Wih_mid, const float* __restrict__ Whh_mid,
     const float* __restrict__ bih_mid, const float* __restrict__ bhh_mid,
     const float* __restrict__ Wi_w, const float* __restrict__ Wi_b,
     const float* __restrict__ We_w, const float* __restrict__ Wt_w,
     const float* __restrict__ Vd_w, const float* __restrict__ Vd_b,
     const float* __restrict__ Wx_w, const float* __restrict__ Wx_b,
     const float* __restrict__ Wh_w, const float* __restrict__ V_w,
     const float* __restrict__ V_b, const float* __restrict__ reg_w,
     const float* __restrict__ reg_b, float* __restrict__ out) {
    extern __shared__ char sm[];
    float* smf = (float*)sm;
    unsigned gen = *((volatile unsigned*)&g_bg);
    const int tid = threadIdx.x;
    const int gtid = blockIdx.x * NT + tid;
    const int gs = NB * NT;
    const int lane = tid & 31, w = tid >> 5;
    const bf z = __float2bfloat16(0.f);

    // ---- S0: split/pack weights, biases, init ----
    for (int i = gtid; i < 2048 * KTG; i += gs) {
        int np = i / KTG, cc = i - np * KTG;
        int r = (np & 3) * 512 + (np >> 2);
        float v = 0.f;
        if (cc < 513)       v = Wih_tg[r * 513 + cc];
        else if (cc < 1025) v = Whh_tg[(r << 9) + cc - 513];
        bsplit(v, g_WtgH[i], g_WtgL[i]);
    }
    for (int i = gtid; i < 2048 * 1024; i += gs) {
        int np = i >> 10, cc = i & 1023;
        int r = (np & 3) * 512 + (np >> 2);
        float vs = cc < 512 ? Wih_sp[(r << 9) + cc] : Whh_sp[(r << 9) + cc - 512];
        float vm = cc < 512 ? Wih_mid[(r << 9) + cc] : Whh_mid[(r << 9) + cc - 512];
        bsplit(vs, g_WspH[i], g_WspL[i]);
        bsplit(vm, g_WmidH[i], g_WmidL[i]);
    }
    for (int i = gtid; i < 1024 * 1024; i += gs) {
        int r = i >> 10, cc = i & 1023;
        float v = r < 512 ? Wt_w[(r << 10) + cc] : Wh_w[((r - 512) << 10) + cc];
        bsplit(v, g_WthH[i], g_WthL[i]);
    }
    for (int i = gtid; i < 512 * 1024; i += gs) bsplit(We_w[i], g_WeH[i], g_WeL[i]);
    for (int i = gtid; i < 512 * 512; i += gs) {
        bsplit(Vd_w[i], g_VdH[i], g_VdL[i]);
        bsplit(Wx_w[i], g_WxH[i], g_WxL[i]);
        bsplit(Wi_w[i], g_WiH[i], g_WiL[i]);
    }
    for (int i = gtid; i < MM2 * 512; i += gs) bsplit(input[i], g_InH[i], g_InL[i]);
    for (int i = gtid; i < 2048; i += gs) {
        g_bt[i] = bih_tg[i] + bhh_tg[i];
        g_bs[i] = bih_sp[i] + bhh_sp[i];
        g_bm[i] = bih_mid[i] + bhh_mid[i];
    }
    for (int i = gtid; i < 256 * 512; i += gs) { g_ht[i] = 0.f; g_ct[i] = 0.f; g_dec[i] = 0.f; }
    for (int i = gtid; i < 256; i += gs) g_lab[i] = label_p[i * (LE + LOOKN) + LE];
    gridbar(gen);

    // ---- S1: wi = input @ Wi^T + Wi_b (12288x512x512), T64 ----
    for (int _t = blockIdx.x; _t < 1536; _t += NB) {
        int bm = (_t >> 3) * 64, bn = (_t & 7) * 64;
        float acc[2][4];
        tc_tile<64, 0>(acc, bm, bn, 512, g_InH, g_InL, 0, 0, g_WiH, g_WiL, sm);
        epi_store<64>(acc, bm, bn, g_wi, 512, Wi_b);
    }
    gridbar(gen);

#pragma unroll 1
    for (int t = 0; t < LOOKN; t++) {
        // PA: pack Atg (split, zero-padded to KTG)
        for (int i = gtid; i < 256 * KTG; i += gs) {
            int b = i / KTG, c = i - b * KTG;
            float v = 0.f;
            if (c == 0)        v = g_lab[b];
            else if (c < 513)  v = g_dec[(b << 9) + c - 1];
            else if (c < 1025) v = g_ht[(b << 9) + c - 513];
            bsplit(v, g_AtgH[i], g_AtgL[i]);
        }
        gridbar(gen);
        // P1: tg gates + LSTM (T64, 128 tiles)
        for (int _t = blockIdx.x; _t < 128; _t += NB) {
            int bm = (_t >> 5) * 64, bn = (_t & 31) * 64;
            float acc[2][4];
            tc_tile<64, 0>(acc, bm, bn, KTG, g_AtgH, g_AtgL, 0, 0, g_WtgH, g_WtgL, sm);
            epi_lstm<64>(acc, bm, bn, g_bt, g_ct, g_ht, g_HtH, g_HtL, g_CtH, g_CtL,
                         0, 0, 0, 0, 0);
        }
        gridbar(gen);
        // P2: wtwh (T32, 128 tiles) + target rowdot + zero inner states
        for (int _t = blockIdx.x; _t < 128; _t += NB) {
            int bm = (_t >> 4) * 32, bn = (_t & 15) * 64;
            float acc[2][4];
            tc_tile<32, 1>(acc, bm, bn, 1024, g_HtH, g_HtL, g_CtH, g_CtL, g_WthH, g_WthL, sm);
            epi_store<32>(acc, bm, bn, g_wtwh, 1024, 0);
        }
        for (int u = blockIdx.x; u < 16; u += NB) {
            int row = u * 16 + w;
            const float* x = g_ht + ((size_t)row << 9);
            float s = 0.f;
#pragma unroll
            for (int k = lane * 4; k < 512; k += 128) {
                float4 xv = *(const float4*)(x + k);
                float4 wv = *(const float4*)(reg_w + k);
                s = fmaf(xv.x, wv.x, s); s = fmaf(xv.y, wv.y, s);
                s = fmaf(xv.z, wv.z, s); s = fmaf(xv.w, wv.w, s);
            }
#pragma unroll
            for (int o = 16; o; o >>= 1) s += __shfl_xor_sync(0xffffffffu, s, o);
            if (lane == 0) { s += reg_b[0]; out[row * LOOKN + t] = s; g_lab[row] = s; }
        }
        for (int i = gtid; i < 256 * 512; i += gs) {
            g_ce[i] = 0.f; g_cm[i] = 0.f;
            g_HeH[0][i] = z; g_HeL[0][i] = z;
            g_CeH[i] = z;    g_CeL[i] = z;
            g_HmH[0][i] = z; g_HmL[0][i] = z;
        }
        gridbar(gen);

        // ---- sp attention loop (with mid-LSTM step l-1 folded into phase A) ----
#pragma unroll 1
        for (int l = 0; l < LE; l++) {
            const int cur = l & 1, nxt = cur ^ 1;
            // Phase A: P3 u-tiles (64 T32) + mid step l-1 (128 T64, if l>0)
            {
                int ntask = 64 + (l > 0 ? 128 : 0);
                for (int _t = blockIdx.x; _t < ntask; _t += NB) {
                    if (_t < 64) {
                        int bm = (_t >> 3) * 32, bn = (_t & 7) * 64;
                        float acc[2][4];
                        tc_tile<32, 1>(acc, bm, bn, 1024, g_HeH[cur], g_HeL[cur],
                                       g_CeH, g_CeL, g_WeH, g_WeL, sm);
                        epi_u<32>(acc, bm, bn, l);
                    } else {
                        int mt = _t - 64;
                        int bm = (mt >> 5) * 64, bn = (mt & 31) * 64;
                        int ms = l - 1, mcur = ms & 1, mnxt = mcur ^ 1;
                        float acc[2][4];
                        tc_tile<64, 1>(acc, bm, bn, 1024, g_MidH + (size_t)ms * 131072,
                                       g_MidL + (size_t)ms * 131072, g_HmH[mcur], g_HmL[mcur],
                                       g_WmidH, g_WmidL, sm);
                        epi_lstm<64>(acc, bm, bn, g_bm, g_cm, 0, g_HmH[mnxt], g_HmL[mnxt],
                                     0, 0, g_mid2, g_M2H, g_M2L, (size_t)ms * 512, LE * 512);
                    }
                }
            }
            gridbar(gen);
            // P4: score = u @ Vd^T + Vd_b (T32, 64 tiles)
            for (int _t = blockIdx.x; _t < 64; _t += NB) {
                int bm = (_t >> 3) * 32, bn = (_t & 7) * 64;
                float acc[2][4];
                tc_tile<32, 0>(acc, bm, bn, 512, g_UH, g_UL, 0, 0, g_VdH, g_VdL, sm);
                epi_store<32>(acc, bm, bn, g_score, 512, Vd_b);
            }
            gridbar(gen);
            // P5: xmod = x * softmax(score), warp-per-row
            for (int rr = blockIdx.x * 16 + w; rr < 256; rr += NB * 16) {
                const float* srow = g_score + ((size_t)rr << 9);
                float vals[16];
                float mx = -1e30f;
#pragma unroll
                for (int i = 0; i < 16; i++) {
                    vals[i] = srow[lane + i * 32];
                    mx = fmaxf(mx, vals[i]);
                }
#pragma unroll
                for (int o = 16; o; o >>= 1) mx = fmaxf(mx, __shfl_xor_sync(0xffffffffu, mx, o));
                float sv = 0.f;
#pragma unroll
                for (int i = 0; i < 16; i++) { vals[i] = expf(vals[i] - mx); sv += vals[i]; }
#pragma unroll
                for (int o = 16; o; o >>= 1) sv += __shfl_xor_sync(0xffffffffu, sv, o);
                float inv = 1.f / sv;
                const float* xr = input + ((size_t)rr * 48 + l) * 512;
#pragma unroll
                for (int i = 0; i < 16; i++) {
                    int c = lane + i * 32;
                    bsplit(xr[c] * vals[i] * inv,
                           g_XmH[((size_t)rr << 9) + c], g_XmL[((size_t)rr << 9) + c]);
                }
            }
            gridbar(gen);
            // P6: sp gates + LSTM (T64, 128 tiles)
            for (int _t = blockIdx.x; _t < 128; _t += NB) {
                int bm = (_t >> 5) * 64, bn = (_t & 31) * 64;
                float acc[2][4];
                tc_tile<64, 1>(acc, bm, bn, 1024, g_XmH, g_XmL, g_HeH[cur], g_HeL[cur],
                               g_WspH, g_WspL, sm);
                epi_lstm<64>(acc, bm, bn, g_bs, g_ce, 0, g_HeH[nxt], g_HeL[nxt],
                             g_CeH, g_CeL, 0, g_MidH, g_MidL, (size_t)l * 131072, 512);
            }
            gridbar(gen);
        }

        // trailing mid step l=47
        {
            int ms = LE - 1, mcur = ms & 1, mnxt = mcur ^ 1;
            for (int _t = blockIdx.x; _t < 128; _t += NB) {
                int bm = (_t >> 5) * 64, bn = (_t & 31) * 64;
                float acc[2][4];
                tc_tile<64, 1>(acc, bm, bn, 1024, g_MidH + (size_t)ms * 131072,
                               g_MidL + (size_t)ms * 131072, g_HmH[mcur], g_HmL[mcur],
                               g_WmidH, g_WmidL, sm);
                epi_lstm<64>(acc, bm, bn, g_bm, g_cm, 0, g_HmH[mnxt], g_HmL[mnxt],
                             0, 0, g_mid2, g_M2H, g_M2L, (size_t)ms * 512, LE * 512);
            }
        }
        gridbar(gen);

        // P8: u2 = tanh(mid2 @ Wx^T + Wx_b + wh) (T64, 1536 tiles)
        for (int _t = blockIdx.x; _t < 1536; _t += NB) {
            int bm = (_t >> 3) * 64, bn = (_t & 7) * 64;
            float acc[2][4];
            tc_tile<64, 0>(acc, bm, bn, 512, g_M2H, g_M2L, 0, 0, g_WxH, g_WxL, sm);
            epi_u2<64>(acc, bm, bn, Wx_b);
        }
        gridbar(gen);
        // P9: sc = u2 @ V_w + V_b
        for (int u = blockIdx.x; u < MM2 / 16; u += NB) {
            int row = u * 16 + w;
            const float* x = g_u2 + ((size_t)row << 9);
            float s = 0.f;
#pragma unroll
            for (int k = lane * 4; k < 512; k += 128) {
                float4 xv = *(const float4*)(x + k);
                float4 wv = *(const float4*)(V_w + k);
                s = fmaf(xv.x, wv.x, s); s = fmaf(xv.y, wv.y, s);
                s = fmaf(xv.z, wv.z, s); s = fmaf(xv.w, wv.w, s);
            }
#pragma unroll
            for (int o = 16; o; o >>= 1) s += __shfl_xor_sync(0xffffffffu, s, o);
            if (lane == 0) g_sc[row] = s + V_b[0];
        }
        gridbar(gen);
        // P10: dec_in
        for (int b = blockIdx.x; b < 256; b += NB) {
            __syncthreads();
            if (tid < LE) smf[tid] = g_sc[b * LE + tid];
            __syncthreads();
            for (int h2 = tid; h2 < 512; h2 += NT) {
                float s = 0.f;
                const float* m2 = g_mid2 + (size_t)b * LE * 512 + h2;
#pragma unroll 8
                for (int ll = 0; ll < LE; ll++) s = fmaf(smf[ll], m2[(size_t)ll * 512], s);
                g_dec[(b << 9) + h2] = s;
            }
        }
        gridbar(gen);
    }
}

extern "C" void kernel_launch(void* const* d_in, const int* in_sizes, int n_in,
                              void* d_out, int out_size) {
    cudaFuncSetAttribute(mega, cudaFuncAttributeMaxDynamicSharedMemorySize, 208896);
    mega<<<NB, NT, 208896>>>(
        (const float*)d_in[0],  (const float*)d_in[1],  (const float*)d_in[2],
        (const float*)d_in[3],  (const float*)d_in[4],  (const float*)d_in[5],
        (const float*)d_in[6],  (const float*)d_in[7],  (const float*)d_in[8],
        (const float*)d_in[9],  (const float*)d_in[10], (const float*)d_in[11],
        (const float*)d_in[12], (const float*)d_in[13], (const float*)d_in[14],
        (const float*)d_in[15], (const float*)d_in[16], (const float*)d_in[17],
        (const float*)d_in[18], (const float*)d_in[19], (const float*)d_in[20],
        (const float*)d_in[21], (const float*)d_in[22], (const float*)d_in[23],
        (const float*)d_in[24], (const float*)d_in[25], (const float*)d_in[26],
        (float*)d_out);
}